// round 3
// baseline (speedup 1.0000x reference)
#include <cuda_runtime.h>
#include <math.h>

#define PH 7
#define PW 7
#define NC 256
#define CPT 4   // channels per thread

// Thread index = (r, cgroup, ph, pw); each thread computes the bilinear
// geometry for one sample position once and applies it to CPT channels.
__global__ void pooler_kernel(
    const float* __restrict__ x0, const float* __restrict__ x1,
    const float* __restrict__ x2, const float* __restrict__ x3,
    const float* __restrict__ boxes, float* __restrict__ out, int R)
{
    int idx = blockIdx.x * blockDim.x + threadIdx.x;
    const int NCG = NC / CPT;
    int total = R * NCG * PH * PW;
    if (idx >= total) return;

    int pw = idx % PW;
    int ph = (idx / PW) % PH;
    int cg = (idx / (PW * PH)) % NCG;
    int r  = idx / (PW * PH * NCG);
    int c0 = cg * CPT;

    // ROI box
    float bx1 = __ldg(&boxes[r * 4 + 0]);
    float by1 = __ldg(&boxes[r * 4 + 1]);
    float bx2 = __ldg(&boxes[r * 4 + 2]);
    float by2 = __ldg(&boxes[r * 4 + 3]);

    // FPN level: floor(4 + log2(sqrt(area)/224 + 1e-6)), clip [2,5], -2
    float area = (bx2 - bx1) * (by2 - by1);
    float s = sqrtf(area);
    float lf = floorf(4.0f + log2f(s / 224.0f + 1e-6f));
    lf = fminf(fmaxf(lf, 2.0f), 5.0f);
    int lvl = (int)lf - 2;

    const float* feat;
    int H;
    float scale;
    switch (lvl) {
        case 0:  feat = x0; H = 200; scale = 0.25f;    break;
        case 1:  feat = x1; H = 100; scale = 0.125f;   break;
        case 2:  feat = x2; H = 50;  scale = 0.0625f;  break;
        default: feat = x3; H = 25;  scale = 0.03125f; break;
    }
    int W = H;
    int HW = H * W;

    int bidx = (2 * r) / R;  // B=2: first half of rois -> batch 0

    float x1s = bx1 * scale, y1s = by1 * scale;
    float x2s = bx2 * scale, y2s = by2 * scale;
    float roi_w = fmaxf(x2s - x1s, 1.0f);
    float roi_h = fmaxf(y2s - y1s, 1.0f);
    float bin_w = roi_w * (1.0f / PW);
    float bin_h = roi_h * (1.0f / PH);

    const float* fbase = feat + ((size_t)bidx * NC + c0) * (size_t)HW;

    // Precompute the 2x2 sample geometry (indices + weights), shared by all CPT channels.
    int   off[4][4];     // [sample][tap] offsets into a channel plane
    float wgt[4][4];     // [sample][tap] weights (0 if empty)
    #pragma unroll
    for (int sy = 0; sy < 2; sy++) {
        float y = y1s + ph * bin_h + (sy + 0.5f) * bin_h * 0.5f;
        bool yempty = (y < -1.0f) || (y > (float)H);
        float ycl = fmaxf(y, 0.0f);
        float yl0 = floorf(ycl);
        int yl, yh; float ly;
        if (yl0 >= (float)(H - 1)) { yl = H - 1; yh = H - 1; ly = 0.0f; }
        else { yl = (int)yl0; yh = yl + 1; ly = ycl - yl0; }
        float hy = 1.0f - ly;

        #pragma unroll
        for (int sx = 0; sx < 2; sx++) {
            float x = x1s + pw * bin_w + (sx + 0.5f) * bin_w * 0.5f;
            bool empty = yempty || (x < -1.0f) || (x > (float)W);
            float xcl = fmaxf(x, 0.0f);
            float xl0 = floorf(xcl);
            int xl, xh; float lx;
            if (xl0 >= (float)(W - 1)) { xl = W - 1; xh = W - 1; lx = 0.0f; }
            else { xl = (int)xl0; xh = xl + 1; lx = xcl - xl0; }
            float hx = 1.0f - lx;

            int si = sy * 2 + sx;
            off[si][0] = yl * W + xl;  off[si][1] = yl * W + xh;
            off[si][2] = yh * W + xl;  off[si][3] = yh * W + xh;
            float e = empty ? 0.0f : 0.25f;   // fold the 2x2 mean into the weights
            wgt[si][0] = hy * hx * e;  wgt[si][1] = hy * lx * e;
            wgt[si][2] = ly * hx * e;  wgt[si][3] = ly * lx * e;
        }
    }

    float acc[CPT];
    #pragma unroll
    for (int k = 0; k < CPT; k++) acc[k] = 0.0f;

    #pragma unroll
    for (int si = 0; si < 4; si++) {
        #pragma unroll
        for (int t = 0; t < 4; t++) {
            int   o = off[si][t];
            float w = wgt[si][t];
            #pragma unroll
            for (int k = 0; k < CPT; k++) {
                acc[k] += w * __ldg(&fbase[(size_t)k * HW + o]);
            }
        }
    }

    size_t obase = (((size_t)r * NC + c0) * PH + ph) * PW + pw;
    #pragma unroll
    for (int k = 0; k < CPT; k++) {
        out[obase + (size_t)k * (PH * PW)] = acc[k];
    }
}

extern "C" void kernel_launch(void* const* d_in, const int* in_sizes, int n_in,
                              void* d_out, int out_size) {
    const float* x0    = (const float*)d_in[0];
    const float* x1    = (const float*)d_in[1];
    const float* x2    = (const float*)d_in[2];
    const float* x3    = (const float*)d_in[3];
    const float* boxes = (const float*)d_in[4];
    float* out = (float*)d_out;

    int R = in_sizes[4] / 4;              // B*N = 1024
    int total = R * (NC / CPT) * PH * PW;
    int threads = 256;
    int blocks = (total + threads - 1) / threads;
    pooler_kernel<<<blocks, threads>>>(x0, x1, x2, x3, boxes, out, R);
}

// round 4
// speedup vs baseline: 1.1536x; 1.1536x over previous
#include <cuda_runtime.h>
#include <math.h>

#define PH 7
#define PW 7
#define NC 256
#define WARPS 8   // warps per block; each warp owns a 32-channel chunk

// Block = one (roi, ph); warp w = channels [w*32, w*32+32).
// Warp lanes 0..27 = (pw, sx, xtap) x-positions along the bin row; the 4
// feature rows needed (yl/yh for 2 y-samples) are loaded with one LDG each,
// so lanes span a small contiguous x-range -> few L1 sectors per load.
// Bin value = 4-lane shfl reduction over (sx, xtap).
__global__ void pooler_kernel(
    const float* __restrict__ x0, const float* __restrict__ x1,
    const float* __restrict__ x2, const float* __restrict__ x3,
    const float* __restrict__ boxes, float* __restrict__ out, int R)
{
    int warp = threadIdx.x >> 5;
    int lane = threadIdx.x & 31;
    int bid  = blockIdx.x;
    int r  = bid / PH;
    int ph = bid % PH;
    int c0 = warp * 32;

    // ROI box
    float bx1 = __ldg(&boxes[r * 4 + 0]);
    float by1 = __ldg(&boxes[r * 4 + 1]);
    float bx2 = __ldg(&boxes[r * 4 + 2]);
    float by2 = __ldg(&boxes[r * 4 + 3]);

    // FPN level: floor(4 + log2(sqrt(area)/224 + 1e-6)), clip [2,5], -2
    float area = (bx2 - bx1) * (by2 - by1);
    float s = sqrtf(area);
    float lf = floorf(4.0f + log2f(s / 224.0f + 1e-6f));
    lf = fminf(fmaxf(lf, 2.0f), 5.0f);
    int lvl = (int)lf - 2;

    const float* feat;
    int H;
    float scale;
    switch (lvl) {
        case 0:  feat = x0; H = 200; scale = 0.25f;    break;
        case 1:  feat = x1; H = 100; scale = 0.125f;   break;
        case 2:  feat = x2; H = 50;  scale = 0.0625f;  break;
        default: feat = x3; H = 25;  scale = 0.03125f; break;
    }
    int W = H;
    size_t HW = (size_t)H * W;

    int bidx = (2 * r) / R;  // B=2: first half of rois -> batch 0

    float x1s = bx1 * scale, y1s = by1 * scale;
    float roi_w = fmaxf(bx2 * scale - x1s, 1.0f);
    float roi_h = fmaxf(by2 * scale - y1s, 1.0f);
    float bin_w = roi_w * (1.0f / PW);
    float bin_h = roi_h * (1.0f / PH);

    // y geometry for this ph: 2 samples -> up to 4 distinct feature rows
    float hy[2], ly[2];
    int rl[2], rh[2];
    #pragma unroll
    for (int sy = 0; sy < 2; sy++) {
        float y = y1s + ph * bin_h + (sy + 0.5f) * bin_h * 0.5f;
        bool ye = (y < -1.0f) || (y > (float)H);
        float yc = fmaxf(y, 0.0f);
        float yl0 = floorf(yc);
        int yl_, yh_; float l;
        if (yl0 >= (float)(H - 1)) { yl_ = H - 1; yh_ = H - 1; l = 0.0f; }
        else { yl_ = (int)yl0; yh_ = yl_ + 1; l = yc - yl0; }
        hy[sy] = ye ? 0.0f : (1.0f - l);
        ly[sy] = ye ? 0.0f : l;
        rl[sy] = yl_ * W;
        rh[sy] = yh_ * W;
    }

    // lane x geometry: lane = pw*4 + sx*2 + xtap  (28 active lanes)
    int pw = lane >> 2;
    int sx = (lane >> 1) & 1;
    int xt = lane & 1;
    float wx = 0.0f;
    int xoff = 0;
    if (lane < 28) {
        float x = x1s + pw * bin_w + (sx + 0.5f) * bin_w * 0.5f;
        bool xe = (x < -1.0f) || (x > (float)W);
        float xc = fmaxf(x, 0.0f);
        float xl0 = floorf(xc);
        int xl_, xh_; float l;
        if (xl0 >= (float)(W - 1)) { xl_ = W - 1; xh_ = W - 1; l = 0.0f; }
        else { xl_ = (int)xl0; xh_ = xl_ + 1; l = xc - xl0; }
        xoff = xt ? xh_ : xl_;
        wx = xe ? 0.0f : (xt ? l : (1.0f - l)) * 0.25f;  // fold 2x2 mean
    }

    const float* base = feat + ((size_t)bidx * NC + c0) * HW;
    const float* p0 = base + rl[0] + xoff;
    const float* p1 = base + rh[0] + xoff;
    const float* p2 = base + rl[1] + xoff;
    const float* p3 = base + rh[1] + xoff;

    size_t obase = ((size_t)r * NC + c0) * (PH * PW) + ph * PW + pw;
    bool writer = ((lane & 3) == 0) && (lane < 28);

    float w0 = wx * hy[0], w1 = wx * ly[0], w2 = wx * hy[1], w3 = wx * ly[1];

    #pragma unroll 4
    for (int k = 0; k < 32; k++) {
        float v = w0 * __ldg(p0) + w1 * __ldg(p1) + w2 * __ldg(p2) + w3 * __ldg(p3);
        v += __shfl_xor_sync(0xffffffffu, v, 1);
        v += __shfl_xor_sync(0xffffffffu, v, 2);
        if (writer) out[obase + (size_t)k * (PH * PW)] = v;
        p0 += HW; p1 += HW; p2 += HW; p3 += HW;
    }
}

extern "C" void kernel_launch(void* const* d_in, const int* in_sizes, int n_in,
                              void* d_out, int out_size) {
    const float* x0    = (const float*)d_in[0];
    const float* x1    = (const float*)d_in[1];
    const float* x2    = (const float*)d_in[2];
    const float* x3    = (const float*)d_in[3];
    const float* boxes = (const float*)d_in[4];
    float* out = (float*)d_out;

    int R = in_sizes[4] / 4;    // B*N = 1024
    int blocks = R * PH;        // one block per (roi, ph)
    pooler_kernel<<<blocks, 32 * WARPS>>>(x0, x1, x2, x3, boxes, out, R);
}